// round 17
// baseline (speedup 1.0000x reference)
#include <cuda_runtime.h>
#include <cuda_fp16.h>
#include <math.h>

// N=50000, E=800000, IN=128, H=8, EMB=32, OUT=16, EF=7
#define MAXN 50000
#define MAXE 800000
#define INF_DIM 128
#define NCOLS 256          // wcat cols: WqA(64) | WkA(64) | Wv(128)
#define CSRB 592           // persistent CSR blocks (148 SM x 4)

typedef unsigned long long u64t;

__device__ __forceinline__ u64t dup2(float x) {
    u64t r; asm("mov.b64 %0, {%1, %1};" : "=l"(r) : "f"(x)); return r;
}
__device__ __forceinline__ u64t pk2(float2 f) {
    u64t r; asm("mov.b64 %0, {%1, %2};" : "=l"(r) : "f"(f.x), "f"(f.y)); return r;
}
__device__ __forceinline__ u64t ffma2(u64t a, u64t b, u64t c) {
    u64t d; asm("fma.rn.f32x2 %0, %1, %2, %3;" : "=l"(d) : "l"(a), "l"(b), "l"(c)); return d;
}
__device__ __forceinline__ float2 unpack2(u64t a) {
    float2 f; asm("mov.b64 {%0, %1}, %2;" : "=f"(f.x), "=f"(f.y) : "l"(a)); return f;
}

// -------- device scratch --------
// g_dcz: [0,MAXN)=deg, [MAXN,2MAXN)=cnt, [2MAXN]=bar1, [2MAXN+1]=scan-done,
//        [2MAXN+2]=ready, [2MAXN+3]=edge work ctr
__device__ int    g_dcz[2 * MAXN + 4];
__device__ int    g_offs[MAXN + 1];
__device__ int    g_bsum[256];
__device__ int    g_bbase[256];
// 32B edge record: word0=src, word1=pad, words2..3=bond(0..3) fp16, words4..5=bond(4..6)+1.0
__device__ __align__(32) unsigned g_erec[(size_t)(MAXE + 1) * 8];
__device__ __half g_aqh[(size_t)MAXN * 64];            // Aq fp16, head-major [N][H][8]
__device__ __half g_akh[(size_t)MAXN * 64];            // Ak fp16, head-major
__device__ __half g_vh [(size_t)MAXN * 128];           // v  fp16 [N][128]
__device__ __half g_wcath[NCOLS * INF_DIM];            // wcat fp16, TRANSPOSED [n=256][k=128]

// ---------------- kernel 1 (side): wcat^T fp16 ----------------
__global__ void wcat_prep_kernel(const float* __restrict__ Wq, const float* __restrict__ Wk,
                                 const float* __restrict__ Wv, const float* __restrict__ Wek,
                                 const float* __restrict__ bek)
{
    int idx = blockIdx.x * blockDim.x + threadIdx.x;
    if (idx < INF_DIM * NCOLS) {
        int i = idx >> 8;        // k
        int c = idx & 255;       // n
        float r;
        if (c < 128) {
            const float* Wx = (c < 64) ? Wq : Wk;
            int cc = c & 63;
            int h = cc >> 3, f = cc & 7;
            const float* ekrow = (f < 7) ? (Wek + f * 256) : bek;
            float acc = 0.f;
            #pragma unroll
            for (int m = 0; m < 32; ++m)
                acc = fmaf(Wx[i * 256 + h * 32 + m], ekrow[h * 32 + m], acc);
            r = acc;
        } else {
            r = Wv[i * 128 + (c - 128)];
        }
        g_wcath[c * INF_DIM + i] = __float2half(r);
    }
}

// ---------------- kernel 2 (side): HMMA GEMM ----------------
__global__ void __launch_bounds__(256) hgemm_kernel(const float* __restrict__ feat, int M)
{
    __shared__ __half As[128][72];
    __shared__ __half Bs[64][72];
    int tid = threadIdx.x;
    int wid = tid >> 5, lane = tid & 31;
    int brow = blockIdx.x * 128;
    int bcol = blockIdx.y * 64;
    int wm = wid >> 1, wn = wid & 1;

    float acc[2][4][4];
    #pragma unroll
    for (int mt = 0; mt < 2; ++mt)
        #pragma unroll
        for (int nt = 0; nt < 4; ++nt)
            #pragma unroll
            for (int r = 0; r < 4; ++r) acc[mt][nt][r] = 0.f;

    #pragma unroll
    for (int kh = 0; kh < 2; ++kh) {
        #pragma unroll
        for (int it = 0; it < 4; ++it) {
            int q = tid + it * 256;
            int r = q >> 3;
            int c8 = (q & 7) * 8;
            int gr = brow + r;
            uint4 val = make_uint4(0, 0, 0, 0);
            if (gr < M) {
                float4 f0 = *(const float4*)(feat + (size_t)gr * 128 + kh * 64 + c8);
                float4 f1 = *(const float4*)(feat + (size_t)gr * 128 + kh * 64 + c8 + 4);
                __half2 h0 = __floats2half2_rn(f0.x, f0.y);
                __half2 h1 = __floats2half2_rn(f0.z, f0.w);
                __half2 h2 = __floats2half2_rn(f1.x, f1.y);
                __half2 h3 = __floats2half2_rn(f1.z, f1.w);
                val.x = *(unsigned*)&h0; val.y = *(unsigned*)&h1;
                val.z = *(unsigned*)&h2; val.w = *(unsigned*)&h3;
            }
            *(uint4*)&As[r][c8] = val;
        }
        #pragma unroll
        for (int it = 0; it < 2; ++it) {
            int q = tid + it * 256;
            int r = q >> 3;
            int c8 = (q & 7) * 8;
            *(uint4*)&Bs[r][c8] = *(const uint4*)(g_wcath + (size_t)(bcol + r) * 128 + kh * 64 + c8);
        }
        __syncthreads();

        #pragma unroll
        for (int ks = 0; ks < 4; ++ks) {
            int k0 = ks * 16;
            unsigned a[2][4];
            #pragma unroll
            for (int mt = 0; mt < 2; ++mt) {
                int row = wm * 32 + mt * 16 + (lane & 15);
                int col = k0 + ((lane >> 4) << 3);
                unsigned addr = (unsigned)__cvta_generic_to_shared(&As[row][col]);
                asm volatile("ldmatrix.sync.aligned.m8n8.x4.shared.b16 {%0,%1,%2,%3}, [%4];"
                             : "=r"(a[mt][0]), "=r"(a[mt][1]), "=r"(a[mt][2]), "=r"(a[mt][3])
                             : "r"(addr));
            }
            unsigned b[2][4];
            #pragma unroll
            for (int g = 0; g < 2; ++g) {
                int nrow = wn * 32 + g * 16 + (lane & 7) + ((lane >> 4) << 3);
                int col = k0 + (lane & 8);
                unsigned addr = (unsigned)__cvta_generic_to_shared(&Bs[nrow][col]);
                asm volatile("ldmatrix.sync.aligned.m8n8.x4.shared.b16 {%0,%1,%2,%3}, [%4];"
                             : "=r"(b[g][0]), "=r"(b[g][1]), "=r"(b[g][2]), "=r"(b[g][3])
                             : "r"(addr));
            }
            #pragma unroll
            for (int mt = 0; mt < 2; ++mt)
                #pragma unroll
                for (int nt = 0; nt < 4; ++nt) {
                    unsigned b0 = b[nt >> 1][(nt & 1) * 2];
                    unsigned b1 = b[nt >> 1][(nt & 1) * 2 + 1];
                    asm volatile(
                        "mma.sync.aligned.m16n8k16.row.col.f32.f16.f16.f32 "
                        "{%0,%1,%2,%3}, {%4,%5,%6,%7}, {%8,%9}, {%0,%1,%2,%3};"
                        : "+f"(acc[mt][nt][0]), "+f"(acc[mt][nt][1]),
                          "+f"(acc[mt][nt][2]), "+f"(acc[mt][nt][3])
                        : "r"(a[mt][0]), "r"(a[mt][1]), "r"(a[mt][2]), "r"(a[mt][3]),
                          "r"(b0), "r"(b1));
                }
        }
        __syncthreads();
    }

    int gcol0 = bcol + wn * 32;
    __half* dsth; int cstart; int stride;
    if (gcol0 < 64)        { dsth = g_aqh; cstart = gcol0;       stride = 64; }
    else if (gcol0 < 128)  { dsth = g_akh; cstart = gcol0 - 64;  stride = 64; }
    else                   { dsth = g_vh;  cstart = gcol0 - 128; stride = 128; }

    #pragma unroll
    for (int mt = 0; mt < 2; ++mt) {
        int row0 = brow + wm * 32 + mt * 16 + (lane >> 2);
        #pragma unroll
        for (int nt = 0; nt < 4; ++nt) {
            int cc = cstart + nt * 8 + (lane & 3) * 2;
            if (row0 < M) {
                __half2 hv = __floats2half2_rn(acc[mt][nt][0], acc[mt][nt][1]);
                *(__half2*)(dsth + (size_t)row0 * stride + cc) = hv;
            }
            if (row0 + 8 < M) {
                __half2 hv = __floats2half2_rn(acc[mt][nt][2], acc[mt][nt][3]);
                *(__half2*)(dsth + (size_t)(row0 + 8) * stride + cc) = hv;
            }
        }
    }
}

// ---------------- kernel 3: persistent CSR build (deg -> scan -> scatter) ----------------
__global__ void __launch_bounds__(256, 4) csr_kernel(
    const int* __restrict__ src, const int* __restrict__ dst,
    const float* __restrict__ bond, int n, int E, int nscanb)
{
    __shared__ int wsum[8];
    int t = threadIdx.x, lane = t & 31, wid = t >> 5;
    int b = blockIdx.x;

    // ---- phase 1: degree atomics ----
    for (int e = b * 256 + t; e < E; e += CSRB * 256)
        atomicAdd(&g_dcz[dst[e]], 1);

    __syncthreads();
    if (t == 0) {
        __threadfence();
        atomicAdd(&g_dcz[2 * MAXN], 1);
        while (*(volatile int*)&g_dcz[2 * MAXN] < CSRB) { }
    }
    __syncthreads();
    __threadfence();

    // ---- phase 2: scan ----
    if (b < nscanb) {
        int i = b * 256 + t;
        int v = (i < n) ? g_dcz[i] : 0;
        int x = v;
        #pragma unroll
        for (int d = 1; d < 32; d <<= 1) {
            int y = __shfl_up_sync(0xffffffffu, x, d);
            if (lane >= d) x += y;
        }
        if (lane == 31) wsum[wid] = x;
        __syncthreads();
        if (wid == 0 && lane < 8) {
            int y = wsum[lane];
            #pragma unroll
            for (int d = 1; d < 8; d <<= 1) {
                int z = __shfl_up_sync(0xffu, y, d);
                if (lane >= d) y += z;
            }
            wsum[lane] = y;
        }
        __syncthreads();
        int excl = ((wid > 0) ? wsum[wid - 1] : 0) + (x - v);
        if (i < n) g_offs[i] = excl;
        if (t == 255) {
            g_bsum[b] = wsum[7];
            __threadfence();
            atomicAdd(&g_dcz[2 * MAXN + 1], 1);
        }
        __syncthreads();
    }

    if (b == 0) {
        if (t == 0) {
            while (*(volatile int*)&g_dcz[2 * MAXN + 1] < nscanb) { }
        }
        __syncthreads();
        __threadfence();
        int vv = (t < nscanb) ? g_bsum[t] : 0;
        int xx = vv;
        #pragma unroll
        for (int d = 1; d < 32; d <<= 1) {
            int y = __shfl_up_sync(0xffffffffu, xx, d);
            if (lane >= d) xx += y;
        }
        if (lane == 31) wsum[wid] = xx;
        __syncthreads();
        if (wid == 0 && lane < 8) {
            int y = wsum[lane];
            #pragma unroll
            for (int d = 1; d < 8; d <<= 1) {
                int z = __shfl_up_sync(0xffu, y, d);
                if (lane >= d) y += z;
            }
            wsum[lane] = y;
        }
        __syncthreads();
        int excl = ((wid > 0) ? wsum[wid - 1] : 0) + (xx - vv);
        if (t < nscanb) g_bbase[t] = excl;
        if (t == 0) {
            g_offs[n] = g_bsum[n >> 8];
            __threadfence();
            atomicExch(&g_dcz[2 * MAXN + 2], 1);
        }
    }

    if (t == 0) {
        while (*(volatile int*)&g_dcz[2 * MAXN + 2] == 0) { }
    }
    __syncthreads();
    __threadfence();

    // ---- phase 3: scatter (single 32B record per edge: one sector) ----
    for (int e = b * 256 + t; e < E; e += CSRB * 256) {
        int d = dst[e];
        int p = g_offs[d] + g_bbase[d >> 8] + atomicAdd(&g_dcz[MAXN + d], 1);
        const float* bp = bond + (size_t)e * 7;
        float b0 = __ldg(bp + 0), b1 = __ldg(bp + 1), b2 = __ldg(bp + 2), b3 = __ldg(bp + 3);
        float b4 = __ldg(bp + 4), b5 = __ldg(bp + 5), b6 = __ldg(bp + 6);
        __half2 h0 = __floats2half2_rn(b0, b1), h1 = __floats2half2_rn(b2, b3);
        __half2 h2 = __floats2half2_rn(b4, b5), h3 = __floats2half2_rn(b6, 1.f);
        uint4 rec0;
        rec0.x = (unsigned)src[e];
        rec0.y = 0u;
        rec0.z = *(unsigned*)&h0;
        rec0.w = *(unsigned*)&h1;
        uint2 rec1;
        rec1.x = *(unsigned*)&h2;
        rec1.y = *(unsigned*)&h3;
        *(uint4*)&g_erec[(size_t)p * 8]     = rec0;
        *(uint2*)&g_erec[(size_t)p * 8 + 4] = rec1;
    }
}

// ---------------- kernel 4: persistent edge attention + aggregation ----------------
// One warp per node (2-node queue pops). Edge record = one 32B sector:
// prefetched uint4 carries next src + bond(0..3); uint2 carries bond(4..6)+1.
__global__ void __launch_bounds__(256, 5) edge_attn_kernel(
    const float* __restrict__ Wefc, const float* __restrict__ befc,
    const float* __restrict__ bias, float* __restrict__ out, int n)
{
    int l = threadIdx.x & 31;
    int h = l >> 2, jl = l & 1;
    int ch = 4 * l;

    __half2 wefh[8][2];
    #pragma unroll
    for (int f = 0; f < 7; ++f) {
        float4 w = *(const float4*)(&Wefc[f * 128 + ch]);
        wefh[f][0] = __floats2half2_rn(w.x, w.y);
        wefh[f][1] = __floats2half2_rn(w.z, w.w);
    }
    {
        float4 w = *(const float4*)(&befc[ch]);
        wefh[7][0] = __floats2half2_rn(w.x, w.y);
        wefh[7][1] = __floats2half2_rn(w.z, w.w);
    }
    float4 b4 = *(const float4*)(&bias[ch]);

    for (;;) {
        int nbase;
        if (l == 0) nbase = atomicAdd(&g_dcz[2 * MAXN + 3], 2);
        nbase = __shfl_sync(0xffffffffu, nbase, 0);
        if (nbase >= n) break;
        int nend = min(nbase + 2, n);

        for (int node = nbase; node < nend; ++node) {
            int start = g_offs[node]     + g_bbase[node >> 8];
            int end   = g_offs[node + 1] + g_bbase[(node + 1) >> 8];

            float2 akf01, akf23;
            {
                uint2 a = *(const uint2*)(g_akh + (size_t)node * 64 + h * 8 + 4 * jl);
                akf01 = __half22float2(*(__half2*)&a.x);
                akf23 = __half22float2(*(__half2*)&a.y);
            }

            float denom = 0.f;
            u64t a2[2] = {0ull, 0ull};

            uint4 r0 = make_uint4(0, 0, 0, 0);
            if (start < end) r0 = *(const uint4*)&g_erec[(size_t)start * 8];

            for (int p = start; p < end; ++p) {
                uint4 r0n = *(const uint4*)&g_erec[(size_t)(p + 1) * 8];   // padded: safe
                uint2 r1  = *(const uint2*)&g_erec[(size_t)p * 8 + 4];

                int cs = (int)r0.x;
                __half2 hb01 = *(__half2*)&r0.z, hb23 = *(__half2*)&r0.w;
                __half2 hb45 = *(__half2*)&r1.x, hb67 = *(__half2*)&r1.y;  // .y of hb67 = 1.0

                uint2 aqr = *(const uint2*)(g_aqh + (size_t)cs * 64 + h * 8 + 4 * jl);
                uint2 vr  = *(const uint2*)(g_vh  + (size_t)cs * 128 + ch);

                // logit (fp32): lane parity owns features 4jl..4jl+3; ONE shfl
                float2 q01 = __half22float2(*(__half2*)&aqr.x);
                float2 q23 = __half22float2(*(__half2*)&aqr.y);
                float2 bb01 = __half22float2(jl ? hb45 : hb01);
                float2 bb23 = __half22float2(jl ? hb67 : hb23);
                float part = bb01.x * (q01.x + akf01.x);
                part = fmaf(bb01.y, q01.y + akf01.y, part);
                part = fmaf(bb23.x, q23.x + akf23.x, part);
                part = fmaf(bb23.y, q23.y + akf23.y, part);
                part += __shfl_xor_sync(0xffffffffu, part, 1);
                float w = __expf(part);
                denom += w;

                // ef = bond @ Wefc + befc (fp16, HFMA2 with half-dup selectors)
                __half2 ef0 = wefh[7][0], ef1 = wefh[7][1];
                __half2 b0d = __low2half2(hb01),  b1d = __high2half2(hb01);
                __half2 b2d = __low2half2(hb23),  b3d = __high2half2(hb23);
                __half2 b4d = __low2half2(hb45),  b5d = __high2half2(hb45);
                __half2 b6d = __low2half2(hb67);
                ef0 = __hfma2(b0d, wefh[0][0], ef0); ef1 = __hfma2(b0d, wefh[0][1], ef1);
                ef0 = __hfma2(b1d, wefh[1][0], ef0); ef1 = __hfma2(b1d, wefh[1][1], ef1);
                ef0 = __hfma2(b2d, wefh[2][0], ef0); ef1 = __hfma2(b2d, wefh[2][1], ef1);
                ef0 = __hfma2(b3d, wefh[3][0], ef0); ef1 = __hfma2(b3d, wefh[3][1], ef1);
                ef0 = __hfma2(b4d, wefh[4][0], ef0); ef1 = __hfma2(b4d, wefh[4][1], ef1);
                ef0 = __hfma2(b5d, wefh[5][0], ef0); ef1 = __hfma2(b5d, wefh[5][1], ef1);
                ef0 = __hfma2(b6d, wefh[6][0], ef0); ef1 = __hfma2(b6d, wefh[6][1], ef1);

                // m = v ⊙ ef (fp16), then fp32 accumulate a2 += w * m
                __half2 m0 = __hmul2(*(__half2*)&vr.x, ef0);
                __half2 m1 = __hmul2(*(__half2*)&vr.y, ef1);
                float2 mf0 = __half22float2(m0);
                float2 mf1 = __half22float2(m1);
                u64t wd = dup2(w);
                a2[0] = ffma2(wd, pk2(mf0), a2[0]);
                a2[1] = ffma2(wd, pk2(mf1), a2[1]);

                r0 = r0n;
            }

            float4 r;
            if (end > start) {
                float inv = 1.0f / denom;
                float2 lo = unpack2(a2[0]), hi = unpack2(a2[1]);
                r.x = fmaf(lo.x, inv, b4.x);
                r.y = fmaf(lo.y, inv, b4.y);
                r.z = fmaf(hi.x, inv, b4.z);
                r.w = fmaf(hi.y, inv, b4.w);
            } else {
                r = b4;
            }
            *(float4*)(&out[(size_t)node * 128 + ch]) = r;
        }
    }
}

// ---------------- host launcher ----------------
extern "C" void kernel_launch(void* const* d_in, const int* in_sizes, int n_in,
                              void* d_out, int out_size)
{
    const float* feat = (const float*)d_in[0];
    const float* bond = (const float*)d_in[1];
    const int*   src  = (const int*)d_in[2];
    const int*   dst  = (const int*)d_in[3];
    const float* Wq   = (const float*)d_in[4];
    const float* Wk   = (const float*)d_in[5];
    const float* Wv   = (const float*)d_in[6];
    const float* Wek  = (const float*)d_in[7];
    const float* bek  = (const float*)d_in[8];
    const float* Wefc = (const float*)d_in[9];
    const float* befc = (const float*)d_in[10];
    const float* bias = (const float*)d_in[11];
    float* out = (float*)d_out;

    int N = in_sizes[0] / INF_DIM;   // 50000
    int E = in_sizes[2];             // 800000
    int nscanb = (N + 255) / 256;    // 196

    void* dcz_ptr = nullptr;
    cudaGetSymbolAddress(&dcz_ptr, g_dcz);

    cudaStream_t s1;
    cudaStreamCreateWithFlags(&s1, cudaStreamNonBlocking);
    cudaEvent_t evZero, evJoin;
    cudaEventCreateWithFlags(&evZero, cudaEventDisableTiming);
    cudaEventCreateWithFlags(&evJoin, cudaEventDisableTiming);

    cudaMemsetAsync(dcz_ptr, 0, (size_t)(2 * MAXN + 4) * sizeof(int), 0);
    cudaEventRecord(evZero, 0);
    cudaStreamWaitEvent(s1, evZero, 0);
    // #1 (side): wcat prep
    wcat_prep_kernel<<<(INF_DIM * NCOLS + 255) / 256, 256, 0, s1>>>(Wq, Wk, Wv, Wek, bek);
    // #2 (side): tensor-core GEMM — overlaps the whole CSR build
    dim3 ggrid((N + 127) / 128, 4);
    hgemm_kernel<<<ggrid, 256, 0, s1>>>(feat, N);
    cudaEventRecord(evJoin, s1);
    // #3 (main): persistent CSR build
    csr_kernel<<<CSRB, 256>>>(src, dst, bond, N, E, nscanb);
    cudaStreamWaitEvent(0, evJoin, 0);
    // #4 (main): persistent edge attention (profiled by ncu)
    edge_attn_kernel<<<148 * 5, 256>>>(Wefc, befc, bias, out, N);

    cudaEventDestroy(evZero);
    cudaEventDestroy(evJoin);
    cudaStreamDestroy(s1);
}